// round 2
// baseline (speedup 1.0000x reference)
#include <cuda_runtime.h>
#include <math.h>

#define N_NODES 50000
#define N_PAD   50016   // padded to 32-row multiple for the GEMM tiler
#define HID     64
#define R_REL   4
#define E_EDGES 200000
#define NCOL    256     // R_REL * 64

// ---- persistent scratch (device globals; no allocations) ----
__device__ float g_x [(size_t)N_PAD * HID];          // current node features
__device__ float g_xl[(size_t)N_PAD * NCOL];         // x @ WL  (all 4 relations)
__device__ float g_xr[(size_t)N_PAD * NCOL];         // x @ WR
__device__ float g_out[(size_t)R_REL * N_NODES * HID];   // unnormalized aggregation
__device__ float g_den[(size_t)R_REL * N_NODES * 4];     // softmax denominators per head

__device__ __forceinline__ float gelu_exact(float v) {
    return 0.5f * v * (1.0f + erff(v * 0.70710678118654752440f));
}

// ============================================================================
// Entry: x = gelu(LayerNorm(emb @ W + b)) ; one warp per node, 2 cols/lane
// ============================================================================
__global__ void __launch_bounds__(256) entry_kernel(
    const float* __restrict__ emb, const float* __restrict__ W,
    const float* __restrict__ b, const float* __restrict__ lng,
    const float* __restrict__ lnb)
{
    int warp = (blockIdx.x * blockDim.x + threadIdx.x) >> 5;
    int lane = threadIdx.x & 31;
    if (warp >= N_NODES) return;
    float2 v = ((const float2*)(emb + (size_t)warp * 64))[lane];
    int c0 = 2 * lane, c1 = c0 + 1;
    float acc0 = b[c0], acc1 = b[c1];
    #pragma unroll 8
    for (int kk = 0; kk < 32; kk++) {
        float ex = __shfl_sync(0xffffffffu, v.x, kk);
        float ey = __shfl_sync(0xffffffffu, v.y, kk);
        float2 wa = ((const float2*)(W + (2 * kk)     * 64))[lane];
        float2 wb = ((const float2*)(W + (2 * kk + 1) * 64))[lane];
        acc0 = fmaf(ex, wa.x, fmaf(ey, wb.x, acc0));
        acc1 = fmaf(ex, wa.y, fmaf(ey, wb.y, acc1));
    }
    // LayerNorm over 64 values (warp-held)
    float s = acc0 + acc1;
    #pragma unroll
    for (int o = 16; o > 0; o >>= 1) s += __shfl_xor_sync(0xffffffffu, s, o);
    float mu = s * (1.0f / 64.0f);
    float d0 = acc0 - mu, d1 = acc1 - mu;
    float q = d0 * d0 + d1 * d1;
    #pragma unroll
    for (int o = 16; o > 0; o >>= 1) q += __shfl_xor_sync(0xffffffffu, q, o);
    float inv = rsqrtf(q * (1.0f / 64.0f) + 1e-5f);
    float y0 = gelu_exact(d0 * inv * lng[c0] + lnb[c0]);
    float y1 = gelu_exact(d1 * inv * lng[c1] + lnb[c1]);
    ((float2*)(g_x + (size_t)warp * 64))[lane] = make_float2(y0, y1);
}

// ============================================================================
// GEMM: out[N,256] = g_x[N,64] @ W[r][64][64] for r=0..3.
// blockIdx.y selects WL->g_xl vs WR->g_xr. 256 thr, 32 rows/block,
// per-thread tile 8 rows x 4 cols (32 accumulators).
// ============================================================================
__global__ void __launch_bounds__(256) gemm_kernel(
    const float* __restrict__ Wl, const float* __restrict__ Wr)
{
    __shared__ float xs[32][64];
    const float* W  = blockIdx.y ? Wr : Wl;
    float*      out = blockIdx.y ? g_xr : g_xl;
    int tid  = threadIdx.x;
    int row0 = blockIdx.x * 32;
    {   // cooperative load: 32x64 floats = 512 float4
        const float4* src = (const float4*)(g_x + (size_t)row0 * 64);
        float4* dst = (float4*)(&xs[0][0]);
        dst[tid]       = src[tid];
        dst[tid + 256] = src[tid + 256];
    }
    __syncthreads();
    int cg = tid & 63;          // column group (4 cols each)
    int rg = tid >> 6;          // row group (8 rows each)
    int c  = cg * 4;            // global col 0..255
    int r  = c >> 6;
    int cc = c & 63;
    const float* Wp = W + r * 4096 + cc;   // + k*64
    int m0 = rg * 8;
    float acc[8][4];
    #pragma unroll
    for (int i = 0; i < 8; i++)
        acc[i][0] = acc[i][1] = acc[i][2] = acc[i][3] = 0.f;
    #pragma unroll 8
    for (int k = 0; k < 64; k++) {
        float4 w = *(const float4*)(Wp + k * 64);
        #pragma unroll
        for (int i = 0; i < 8; i++) {
            float xv = xs[m0 + i][k];
            acc[i][0] = fmaf(xv, w.x, acc[i][0]);
            acc[i][1] = fmaf(xv, w.y, acc[i][1]);
            acc[i][2] = fmaf(xv, w.z, acc[i][2]);
            acc[i][3] = fmaf(xv, w.w, acc[i][3]);
        }
    }
    #pragma unroll
    for (int i = 0; i < 8; i++) {
        size_t n = (size_t)(row0 + m0 + i);
        *(float4*)(out + n * NCOL + c) =
            make_float4(acc[i][0], acc[i][1], acc[i][2], acc[i][3]);
    }
}

// ============================================================================
// Zero the aggregation buffers
// ============================================================================
__global__ void zero_kernel() {
    size_t i = blockIdx.x * (size_t)blockDim.x + threadIdx.x;
    size_t stride = (size_t)gridDim.x * blockDim.x;
    float4 z = make_float4(0.f, 0.f, 0.f, 0.f);
    const size_t n1 = (size_t)R_REL * N_NODES * 16;  // g_out as float4
    for (size_t j = i; j < n1; j += stride) ((float4*)g_out)[j] = z;
    const size_t n2 = (size_t)R_REL * N_NODES;       // g_den as float4
    for (size_t j = i; j < n2; j += stride) ((float4*)g_den)[j] = z;
}

// ============================================================================
// Edge pass: one 16-lane group per edge (2 edges/warp), 4 floats/lane.
// e_h = sum_c leakyrelu(xl[src]+xr[dst]) * att ; a = exp(e) (no max-subtract:
// normalization is linear, inputs LayerNorm-bounded -> no overflow).
// atomically: den[dst,h] += a ; out[dst,:] += a * xl[src,:]
// ============================================================================
__global__ void __launch_bounds__(256) edge_kernel(
    const int* __restrict__ ei, const float* __restrict__ att_base, int layer)
{
    __shared__ float s_att[64];
    int r = blockIdx.y;
    if (threadIdx.x < 64)
        s_att[threadIdx.x] = att_base[(layer * R_REL + r) * 64 + threadIdx.x];
    __syncthreads();

    int warp = (blockIdx.x * blockDim.x + threadIdx.x) >> 5;
    int lane = threadIdx.x & 31;
    int sub  = lane >> 4;
    int l    = lane & 15;
    int eid  = warp * 2 + sub;
    const int EN = E_EDGES + N_NODES;      // even -> whole warps in range
    if (eid >= EN) return;

    const int* srcp = ei + (size_t)r * 2 * E_EDGES;
    const int* dstp = srcp + E_EDGES;
    int s, d;
    if (eid < E_EDGES) { s = srcp[eid]; d = dstp[eid]; }
    else               { s = eid - E_EDGES; d = s; }    // self-loop

    float4 a4 = *(const float4*)(g_xl + (size_t)s * NCOL + r * 64 + l * 4);
    float4 b4 = *(const float4*)(g_xr + (size_t)d * NCOL + r * 64 + l * 4);
    float m0 = a4.x + b4.x, m1 = a4.y + b4.y, m2 = a4.z + b4.z, m3 = a4.w + b4.w;
    m0 = m0 > 0.f ? m0 : 0.2f * m0;
    m1 = m1 > 0.f ? m1 : 0.2f * m1;
    m2 = m2 > 0.f ? m2 : 0.2f * m2;
    m3 = m3 > 0.f ? m3 : 0.2f * m3;
    int h  = l >> 2;
    int cb = h * 16 + (l & 3) * 4;
    float p = m0 * s_att[cb] + m1 * s_att[cb + 1] + m2 * s_att[cb + 2] + m3 * s_att[cb + 3];
    p += __shfl_xor_sync(0xffffffffu, p, 1);
    p += __shfl_xor_sync(0xffffffffu, p, 2);   // all 4 lanes of head h hold e_h
    float a = expf(p);
    if ((l & 3) == 0)
        atomicAdd(g_den + ((size_t)r * N_NODES + d) * 4 + h, a);
    float* op = g_out + ((size_t)r * N_NODES + d) * 64 + l * 4;
    asm volatile("red.global.add.v4.f32 [%0], {%1,%2,%3,%4};"
                 :: "l"(op), "f"(a * a4.x), "f"(a * a4.y),
                    "f"(a * a4.z), "f"(a * a4.w) : "memory");
}

// ============================================================================
// Combine: x = LayerNorm(gelu( mean_r(out_r/den_r + bias_r) ))
// one warp per node, 2 cols/lane
// ============================================================================
__global__ void __launch_bounds__(256) combine_kernel(
    const float* __restrict__ bias_base, const float* __restrict__ ng,
    const float* __restrict__ nb, int layer, int final_layer, float* __restrict__ dout)
{
    int warp = (blockIdx.x * blockDim.x + threadIdx.x) >> 5;
    int lane = threadIdx.x & 31;
    if (warp >= N_NODES) return;
    int c0 = 2 * lane, c1 = c0 + 1;
    int h  = lane >> 3;                    // head of both c0,c1
    float s0 = 0.f, s1 = 0.f;
    #pragma unroll
    for (int r = 0; r < R_REL; r++) {
        float2 o = ((const float2*)(g_out + ((size_t)r * N_NODES + warp) * 64))[lane];
        float invd = 1.0f / g_den[((size_t)r * N_NODES + warp) * 4 + h];
        const float* bs = bias_base + (layer * R_REL + r) * 64;
        s0 += fmaf(o.x, invd, bs[c0]);
        s1 += fmaf(o.y, invd, bs[c1]);
    }
    s0 = gelu_exact(s0 * 0.25f);
    s1 = gelu_exact(s1 * 0.25f);
    float s = s0 + s1;
    #pragma unroll
    for (int o = 16; o > 0; o >>= 1) s += __shfl_xor_sync(0xffffffffu, s, o);
    float mu = s * (1.0f / 64.0f);
    float d0 = s0 - mu, d1 = s1 - mu;
    float q = d0 * d0 + d1 * d1;
    #pragma unroll
    for (int o = 16; o > 0; o >>= 1) q += __shfl_xor_sync(0xffffffffu, q, o);
    float inv = rsqrtf(q * (1.0f / 64.0f) + 1e-5f);
    float y0 = d0 * inv * ng[c0] + nb[c0];
    float y1 = d1 * inv * ng[c1] + nb[c1];
    float* xout = final_layer ? dout : g_x;
    ((float2*)(xout + (size_t)warp * 64))[lane] = make_float2(y0, y1);
}

// ============================================================================
extern "C" void kernel_launch(void* const* d_in, const int* in_sizes, int n_in,
                              void* d_out, int out_size)
{
    const float* emb       = (const float*)d_in[0];
    const float* entry_w   = (const float*)d_in[1];
    const float* entry_b   = (const float*)d_in[2];
    const float* entry_lng = (const float*)d_in[3];
    const float* entry_lnb = (const float*)d_in[4];
    const float* conv_wl   = (const float*)d_in[5];   // [2,4,64,64]
    const float* conv_wr   = (const float*)d_in[6];
    const float* conv_att  = (const float*)d_in[7];   // [2,4,4,16]
    const float* conv_bias = (const float*)d_in[8];   // [2,4,64]
    const float* norm_g    = (const float*)d_in[9];
    const float* norm_b    = (const float*)d_in[10];
    const int*   edge_idx  = (const int*)d_in[11];    // [4,2,200000]

    entry_kernel<<<(N_NODES + 7) / 8, 256>>>(emb, entry_w, entry_b, entry_lng, entry_lnb);

    const int gemm_blocks = N_PAD / 32;                   // 1563
    const int edge_blocks = (E_EDGES + N_NODES) / 16;     // 15625 (2 edges/warp, 8 warps/blk)

    for (int layer = 0; layer < 2; layer++) {
        gemm_kernel<<<dim3(gemm_blocks, 2), 256>>>(conv_wl + layer * R_REL * 4096,
                                                   conv_wr + layer * R_REL * 4096);
        zero_kernel<<<2048, 256>>>();
        edge_kernel<<<dim3(edge_blocks, R_REL), 256>>>(edge_idx, conv_att, layer);
        combine_kernel<<<(N_NODES + 7) / 8, 256>>>(conv_bias, norm_g, norm_b,
                                                   layer, layer == 1, (float*)d_out);
    }
}

// round 7
// speedup vs baseline: 1.1973x; 1.1973x over previous
#include <cuda_runtime.h>
#include <math.h>

#define N_NODES 50000
#define N_PAD   50016   // padded to 32-row multiple for the GEMM tiler
#define HID     64
#define R_REL   4
#define E_EDGES 200000
#define EN_TOT  (E_EDGES + N_NODES)          // 250000 edges incl self-loops
#define EGRP    (EN_TOT / 2)                 // 125000 2-edge groups per relation
#define EBLK    ((EGRP + 15) / 16)           // 7813 blocks per relation

// ---- persistent scratch (device globals; no allocations) ----
__device__ float g_x [(size_t)N_PAD * HID];            // current node features
__device__ float g_xl[(size_t)R_REL * N_PAD * HID];    // [r][node][64]
__device__ float g_xr[(size_t)R_REL * N_PAD * HID];    // [r][node][64]
__device__ float g_out[(size_t)R_REL * N_NODES * HID]; // unnormalized aggregation
__device__ float g_den[(size_t)R_REL * N_NODES * 4];   // softmax denominators per head

__device__ __forceinline__ float gelu_exact(float v) {
    return 0.5f * v * (1.0f + erff(v * 0.70710678118654752440f));
}
__device__ __forceinline__ unsigned long long pack2(float lo, float hi) {
    unsigned long long r;
    asm("mov.b64 %0, {%1,%2};" : "=l"(r) : "f"(lo), "f"(hi));
    return r;
}
#define FMA2(d, a, b) asm("fma.rn.f32x2 %0, %1, %2, %0;" : "+l"(d) : "l"(a), "l"(b))

// ============================================================================
// Entry: x = gelu(LayerNorm(emb @ W + b)) ; one warp per node, 2 cols/lane
// ============================================================================
__global__ void __launch_bounds__(256) entry_kernel(
    const float* __restrict__ emb, const float* __restrict__ W,
    const float* __restrict__ b, const float* __restrict__ lng,
    const float* __restrict__ lnb)
{
    int warp = (blockIdx.x * blockDim.x + threadIdx.x) >> 5;
    int lane = threadIdx.x & 31;
    if (warp >= N_NODES) return;
    float2 v = ((const float2*)(emb + (size_t)warp * 64))[lane];
    int c0 = 2 * lane, c1 = c0 + 1;
    float acc0 = b[c0], acc1 = b[c1];
    #pragma unroll 8
    for (int kk = 0; kk < 32; kk++) {
        float ex = __shfl_sync(0xffffffffu, v.x, kk);
        float ey = __shfl_sync(0xffffffffu, v.y, kk);
        float2 wa = ((const float2*)(W + (2 * kk)     * 64))[lane];
        float2 wb = ((const float2*)(W + (2 * kk + 1) * 64))[lane];
        acc0 = fmaf(ex, wa.x, fmaf(ey, wb.x, acc0));
        acc1 = fmaf(ex, wa.y, fmaf(ey, wb.y, acc1));
    }
    float s = acc0 + acc1;
    #pragma unroll
    for (int o = 16; o > 0; o >>= 1) s += __shfl_xor_sync(0xffffffffu, s, o);
    float mu = s * (1.0f / 64.0f);
    float d0 = acc0 - mu, d1 = acc1 - mu;
    float q = d0 * d0 + d1 * d1;
    #pragma unroll
    for (int o = 16; o > 0; o >>= 1) q += __shfl_xor_sync(0xffffffffu, q, o);
    float inv = rsqrtf(q * (1.0f / 64.0f) + 1e-5f);
    float y0 = gelu_exact(d0 * inv * lng[c0] + lnb[c0]);
    float y1 = gelu_exact(d1 * inv * lng[c1] + lnb[c1]);
    ((float2*)(g_x + (size_t)warp * 64))[lane] = make_float2(y0, y1);
}

// ============================================================================
// GEMM via packed fma.rn.f32x2: out[r][N,64] = g_x[N,64] @ W[r][64][64].
// blockIdx.y: WL->g_xl vs WR->g_xr. 256 thr, 32 rows/block.
// Per-thread: 8 rows (as 4 packed row-pairs) x 4 cols = 16 b64 accumulators.
// x tile staged TRANSPOSED in smem so a row-pair is a single broadcast LDS.64.
// ============================================================================
__global__ void __launch_bounds__(256) gemm_kernel(
    const float* __restrict__ Wl, const float* __restrict__ Wr)
{
    __shared__ float xs[64][34];   // [k][row], stride 34 (even -> 8B aligned pairs)
    const float* W  = blockIdx.y ? Wr : Wl;
    float*      out = blockIdx.y ? g_xr : g_xl;
    int tid  = threadIdx.x;
    int row0 = blockIdx.x * 32;
    {   // stage + transpose: 32x64 floats = 512 float4
        const float4* src = (const float4*)(g_x + (size_t)row0 * 64);
        #pragma unroll
        for (int t = 0; t < 2; t++) {
            int j = tid + t * 256;
            float4 v = src[j];
            int n  = j >> 4;           // row 0..31
            int k0 = (j & 15) * 4;     // k base
            xs[k0 + 0][n] = v.x; xs[k0 + 1][n] = v.y;
            xs[k0 + 2][n] = v.z; xs[k0 + 3][n] = v.w;
        }
    }
    __syncthreads();
    int cg = tid & 63;            // column group (4 cols)
    int rg = tid >> 6;            // row group (8 rows)
    int c  = cg * 4;              // global col 0..255
    int r  = c >> 6;              // relation
    int cc = c & 63;
    const float* Wp = W + r * 4096 + cc;
    int m0 = rg * 8;
    unsigned long long acc[4][4]; // [rowpair][col]
    #pragma unroll
    for (int i = 0; i < 4; i++)
        acc[i][0] = acc[i][1] = acc[i][2] = acc[i][3] = 0ull;
    #pragma unroll 4
    for (int k = 0; k < 64; k++) {
        float4 w = *(const float4*)(Wp + k * 64);
        unsigned long long w0 = pack2(w.x, w.x);
        unsigned long long w1 = pack2(w.y, w.y);
        unsigned long long w2 = pack2(w.z, w.z);
        unsigned long long w3 = pack2(w.w, w.w);
        #pragma unroll
        for (int i = 0; i < 4; i++) {
            unsigned long long xp = *(const unsigned long long*)(&xs[k][m0 + 2 * i]);
            FMA2(acc[i][0], xp, w0);
            FMA2(acc[i][1], xp, w1);
            FMA2(acc[i][2], xp, w2);
            FMA2(acc[i][3], xp, w3);
        }
    }
    float* obase = out + (size_t)r * N_PAD * 64 + cc;
    #pragma unroll
    for (int i = 0; i < 4; i++) {
        float lo[4], hi[4];
        #pragma unroll
        for (int j = 0; j < 4; j++)
            asm("mov.b64 {%0,%1}, %2;" : "=f"(lo[j]), "=f"(hi[j]) : "l"(acc[i][j]));
        size_t ra = (size_t)(row0 + m0 + 2 * i);
        *(float4*)(obase + ra * 64)       = make_float4(lo[0], lo[1], lo[2], lo[3]);
        *(float4*)(obase + (ra + 1) * 64) = make_float4(hi[0], hi[1], hi[2], hi[3]);
    }
}

// ============================================================================
// Zero the aggregation buffers (only needed once, before layer 0)
// ============================================================================
__global__ void zero_kernel() {
    size_t i = blockIdx.x * (size_t)blockDim.x + threadIdx.x;
    size_t stride = (size_t)gridDim.x * blockDim.x;
    float4 z = make_float4(0.f, 0.f, 0.f, 0.f);
    const size_t n1 = (size_t)R_REL * N_NODES * 16;  // g_out as float4
    for (size_t j = i; j < n1; j += stride) ((float4*)g_out)[j] = z;
    const size_t n2 = (size_t)R_REL * N_NODES;       // g_den as float4
    for (size_t j = i; j < n2; j += stride) ((float4*)g_den)[j] = z;
}

// ============================================================================
// Edge pass, relation-phased: 1D grid, r = blockIdx.x / EBLK so relations run
// as sequential waves (per-phase working set ~38MB -> L2 resident).
// Each 16-lane group handles 2 edges; all 4 gathers issued before use.
// a = exp(e) without max-subtract (normalization is linear; LN-bounded inputs).
// ============================================================================
__global__ void __launch_bounds__(256) edge_kernel(
    const int* __restrict__ ei, const float* __restrict__ att_base, int layer)
{
    __shared__ float s_att[64];
    int r  = blockIdx.x / EBLK;
    int bx = blockIdx.x % EBLK;
    if (threadIdx.x < 64)
        s_att[threadIdx.x] = att_base[(layer * R_REL + r) * 64 + threadIdx.x];
    __syncthreads();

    int grp = (bx * 256 + threadIdx.x) >> 4;    // 2-edge group within relation
    if (grp >= EGRP) return;
    int l = threadIdx.x & 15;

    const int* srcp = ei + (size_t)r * 2 * E_EDGES;
    const int* dstp = srcp + E_EDGES;
    const float* xl = g_xl + (size_t)r * N_PAD * 64;
    const float* xr = g_xr + (size_t)r * N_PAD * 64;
    float* outb = g_out + (size_t)r * N_NODES * 64;
    float* denb = g_den + (size_t)r * N_NODES * 4;

    int e0 = grp * 2, e1 = e0 + 1;
    int s0, d0, s1, d1;
    if (e0 < E_EDGES) { s0 = srcp[e0]; d0 = dstp[e0]; }
    else              { s0 = e0 - E_EDGES; d0 = s0; }
    if (e1 < E_EDGES) { s1 = srcp[e1]; d1 = dstp[e1]; }
    else              { s1 = e1 - E_EDGES; d1 = s1; }

    float4 a0 = *(const float4*)(xl + (size_t)s0 * 64 + l * 4);
    float4 b0 = *(const float4*)(xr + (size_t)d0 * 64 + l * 4);
    float4 a1 = *(const float4*)(xl + (size_t)s1 * 64 + l * 4);
    float4 b1 = *(const float4*)(xr + (size_t)d1 * 64 + l * 4);

    int h  = l >> 2;
    int cb = h * 16 + (l & 3) * 4;
    float w0 = s_att[cb], w1 = s_att[cb + 1], w2 = s_att[cb + 2], w3 = s_att[cb + 3];

    #pragma unroll
    for (int t = 0; t < 2; t++) {
        float4 a4 = t ? a1 : a0;
        float4 b4 = t ? b1 : b0;
        int d = t ? d1 : d0;
        float m0 = a4.x + b4.x, m1 = a4.y + b4.y, m2 = a4.z + b4.z, m3 = a4.w + b4.w;
        m0 = m0 > 0.f ? m0 : 0.2f * m0;
        m1 = m1 > 0.f ? m1 : 0.2f * m1;
        m2 = m2 > 0.f ? m2 : 0.2f * m2;
        m3 = m3 > 0.f ? m3 : 0.2f * m3;
        float p = fmaf(m0, w0, fmaf(m1, w1, fmaf(m2, w2, m3 * w3)));
        p += __shfl_xor_sync(0xffffffffu, p, 1);
        p += __shfl_xor_sync(0xffffffffu, p, 2);  // 4 lanes of head h hold e_h
        float a = __expf(p);
        if ((l & 3) == 0)
            atomicAdd(denb + (size_t)d * 4 + h, a);
        float* op = outb + (size_t)d * 64 + l * 4;
        asm volatile("red.global.add.v4.f32 [%0], {%1,%2,%3,%4};"
                     :: "l"(op), "f"(a * a4.x), "f"(a * a4.y),
                        "f"(a * a4.z), "f"(a * a4.w) : "memory");
    }
}

// ============================================================================
// Combine: x = LayerNorm(gelu( mean_r(out_r/den_r + bias_r) ))
// one warp per node, 2 cols/lane. Re-zeroes g_out/g_den for the next layer
// (lines already resident from the reads).
// ============================================================================
__global__ void __launch_bounds__(256) combine_kernel(
    const float* __restrict__ bias_base, const float* __restrict__ ng,
    const float* __restrict__ nb, int layer, int final_layer, float* __restrict__ dout)
{
    int warp = (blockIdx.x * blockDim.x + threadIdx.x) >> 5;
    int lane = threadIdx.x & 31;
    if (warp >= N_NODES) return;
    int c0 = 2 * lane, c1 = c0 + 1;
    int h  = lane >> 3;
    float s0 = 0.f, s1 = 0.f;
    #pragma unroll
    for (int r = 0; r < R_REL; r++) {
        float2* op = (float2*)(g_out + ((size_t)r * N_NODES + warp) * 64) + lane;
        float2 o = *op;
        float invd = 1.0f / g_den[((size_t)r * N_NODES + warp) * 4 + h];
        const float* bs = bias_base + (layer * R_REL + r) * 64;
        s0 += fmaf(o.x, invd, bs[c0]);
        s1 += fmaf(o.y, invd, bs[c1]);
        if (!final_layer) *op = make_float2(0.f, 0.f);   // re-zero for next layer
    }
    if (!final_layer && lane < 16) {
        int rr = lane >> 2, hh = lane & 3;
        g_den[((size_t)rr * N_NODES + warp) * 4 + hh] = 0.f;
    }
    s0 = gelu_exact(s0 * 0.25f);
    s1 = gelu_exact(s1 * 0.25f);
    float s = s0 + s1;
    #pragma unroll
    for (int o = 16; o > 0; o >>= 1) s += __shfl_xor_sync(0xffffffffu, s, o);
    float mu = s * (1.0f / 64.0f);
    float d0 = s0 - mu, d1 = s1 - mu;
    float q = d0 * d0 + d1 * d1;
    #pragma unroll
    for (int o = 16; o > 0; o >>= 1) q += __shfl_xor_sync(0xffffffffu, q, o);
    float inv = rsqrtf(q * (1.0f / 64.0f) + 1e-5f);
    float y0 = d0 * inv * ng[c0] + nb[c0];
    float y1 = d1 * inv * ng[c1] + nb[c1];
    float* xout = final_layer ? dout : g_x;
    ((float2*)(xout + (size_t)warp * 64))[lane] = make_float2(y0, y1);
}

// ============================================================================
extern "C" void kernel_launch(void* const* d_in, const int* in_sizes, int n_in,
                              void* d_out, int out_size)
{
    const float* emb       = (const float*)d_in[0];
    const float* entry_w   = (const float*)d_in[1];
    const float* entry_b   = (const float*)d_in[2];
    const float* entry_lng = (const float*)d_in[3];
    const float* entry_lnb = (const float*)d_in[4];
    const float* conv_wl   = (const float*)d_in[5];   // [2,4,64,64]
    const float* conv_wr   = (const float*)d_in[6];
    const float* conv_att  = (const float*)d_in[7];   // [2,4,4,16]
    const float* conv_bias = (const float*)d_in[8];   // [2,4,64]
    const float* norm_g    = (const float*)d_in[9];
    const float* norm_b    = (const float*)d_in[10];
    const int*   edge_idx  = (const int*)d_in[11];    // [4,2,200000]

    zero_kernel<<<2048, 256>>>();
    entry_kernel<<<(N_NODES + 7) / 8, 256>>>(emb, entry_w, entry_b, entry_lng, entry_lnb);

    const int gemm_blocks = N_PAD / 32;               // 1563

    for (int layer = 0; layer < 2; layer++) {
        gemm_kernel<<<dim3(gemm_blocks, 2), 256>>>(conv_wl + layer * R_REL * 4096,
                                                   conv_wr + layer * R_REL * 4096);
        edge_kernel<<<R_REL * EBLK, 256>>>(edge_idx, conv_att, layer);
        combine_kernel<<<(N_NODES + 7) / 8, 256>>>(conv_bias, norm_g, norm_b,
                                                   layer, layer == 1, (float*)d_out);
    }
}